// round 14
// baseline (speedup 1.0000x reference)
#include <cuda_runtime.h>
#include <cstdint>
#include <cmath>

// Problem constants (fixed by the reference)
#define D_MODEL   1024
#define NUM_HEADS 16
#define HEAD_DIM  64
#define B_SZ      2
#define SEQ       2048
#define M_TOT     (B_SZ * SEQ)   // 4096 rows for all projection GEMMs

// Scratch (allocation-free rule: __device__ globals). 4 x 16 MB = 64 MB.
__device__ float g_Q[(size_t)M_TOT * D_MODEL];
__device__ float g_K[(size_t)M_TOT * D_MODEL];
__device__ float g_V[(size_t)M_TOT * D_MODEL];
__device__ float g_C[(size_t)M_TOT * D_MODEL];

// ---------------------------------------------------------------------------
// tf32 / cp.async helpers
// ---------------------------------------------------------------------------
__device__ __forceinline__ float f2tf32(float x) {
    asm("cvt.rna.tf32.f32 %0, %0;" : "+f"(x));
    return x;
}

__device__ __forceinline__ void mma_tf32(float& c0, float& c1, float& c2, float& c3,
                                         float a0, float a1, float a2, float a3,
                                         float b0, float b1)
{
    asm volatile(
        "mma.sync.aligned.m16n8k8.row.col.f32.tf32.tf32.f32 "
        "{%0,%1,%2,%3}, {%4,%5,%6,%7}, {%8,%9}, {%0,%1,%2,%3};\n"
        : "+f"(c0), "+f"(c1), "+f"(c2), "+f"(c3)
        : "r"(__float_as_uint(a0)), "r"(__float_as_uint(a1)),
          "r"(__float_as_uint(a2)), "r"(__float_as_uint(a3)),
          "r"(__float_as_uint(b0)), "r"(__float_as_uint(b1)));
}

__device__ __forceinline__ void cp_async16(uint32_t dst, const void* src) {
    asm volatile("cp.async.cg.shared.global [%0], [%1], 16;\n" :: "r"(dst), "l"(src));
}
#define CP_COMMIT() asm volatile("cp.async.commit_group;\n" ::: "memory")
#define CP_WAIT(n)  asm volatile("cp.async.wait_group %0;\n" :: "n"(n) : "memory")

// ---------------------------------------------------------------------------
// GEMM + bias (tf32 tensor cores, cp.async 3-stage pipeline, 3 CTAs/SM)
// (unchanged — proven at 553.9us)
// ---------------------------------------------------------------------------
#define GEMM_M   4096
#define GEMM_N   1024
#define GEMM_K   1024
#define AP       20
#define BPITCH   132
#define A_STAGE  (128 * AP)     // 2560 floats
#define B_STAGE  (16 * BPITCH)  // 2112 floats
#define NSTAGE   3
#define GEMM_SMEM_FLOATS (NSTAGE * (A_STAGE + B_STAGE))   // 14016 -> 56064 B

__device__ __forceinline__ void gemm_issue_stage(
    uint32_t smem_u32, int s, int k0, int tid,
    const float* __restrict__ X, const float* __restrict__ W,
    int m0, int n0)
{
    #pragma unroll
    for (int i = 0; i < 4; i++) {
        const int idx = i * 128 + tid;
        const int m   = idx >> 2;
        const int ko  = (idx & 3) * 4;
        const float* src = X + (size_t)(m0 + m) * GEMM_K + k0 + ko;
        uint32_t dst = smem_u32 + (uint32_t)((s * A_STAGE + m * AP + ko) * 4);
        cp_async16(dst, src);
    }
    #pragma unroll
    for (int i = 0; i < 4; i++) {
        const int idx = i * 128 + tid;
        const int k   = idx >> 5;
        const int n4  = (idx & 31) * 4;
        const float* src = W + (size_t)(k0 + k) * GEMM_N + n0 + n4;
        uint32_t dst = smem_u32 +
            (uint32_t)((NSTAGE * A_STAGE + s * B_STAGE + k * BPITCH + n4) * 4);
        cp_async16(dst, src);
    }
}

__device__ __forceinline__ void gemm_body(
    const float* __restrict__ X, const float* __restrict__ W,
    const float* __restrict__ bias, float* __restrict__ Y)
{
    extern __shared__ __align__(16) float gsm[];
    uint32_t smem_u32 = (uint32_t)__cvta_generic_to_shared(gsm);

    const int tid  = threadIdx.x;
    const int lane = tid & 31;
    const int warp = tid >> 5;           // 0..3
    const int wm   = (warp >> 1) * 64;
    const int wn   = (warp & 1) * 64;
    const int r    = lane >> 2;
    const int c    = lane & 3;

    const int m0 = blockIdx.y * 128;
    const int n0 = blockIdx.x * 128;

    float acc[4][8][4];
    #pragma unroll
    for (int i = 0; i < 4; i++)
        #pragma unroll
        for (int j = 0; j < 8; j++)
            #pragma unroll
            for (int q = 0; q < 4; q++) acc[i][j][q] = 0.f;

    const int nIter = GEMM_K / 16;   // 64

    #pragma unroll
    for (int s = 0; s < NSTAGE - 1; s++) {
        gemm_issue_stage(smem_u32, s, s * 16, tid, X, W, m0, n0);
        CP_COMMIT();
    }

    for (int it = 0; it < nIter; it++) {
        CP_WAIT(NSTAGE - 2);
        __syncthreads();

        if (it + NSTAGE - 1 < nIter)
            gemm_issue_stage(smem_u32, (it + NSTAGE - 1) % NSTAGE,
                             (it + NSTAGE - 1) * 16, tid, X, W, m0, n0);
        CP_COMMIT();

        const int buf = it % NSTAGE;
        const float* Ab = gsm + buf * A_STAGE;
        const float* Bb = gsm + NSTAGE * A_STAGE + buf * B_STAGE;

        #pragma unroll
        for (int s = 0; s < 2; s++) {
            const int kb = s * 8;
            float af[4][4], bf[8][2];
            #pragma unroll
            for (int mi = 0; mi < 4; mi++) {
                const int mb = wm + 16 * mi;
                af[mi][0] = f2tf32(Ab[(mb + r    ) * AP + kb + c    ]);
                af[mi][1] = f2tf32(Ab[(mb + r + 8) * AP + kb + c    ]);
                af[mi][2] = f2tf32(Ab[(mb + r    ) * AP + kb + c + 4]);
                af[mi][3] = f2tf32(Ab[(mb + r + 8) * AP + kb + c + 4]);
            }
            #pragma unroll
            for (int ni = 0; ni < 8; ni++) {
                const int nb = wn + 8 * ni;
                bf[ni][0] = f2tf32(Bb[(kb + c    ) * BPITCH + nb + r]);
                bf[ni][1] = f2tf32(Bb[(kb + c + 4) * BPITCH + nb + r]);
            }
            #pragma unroll
            for (int mi = 0; mi < 4; mi++)
                #pragma unroll
                for (int ni = 0; ni < 8; ni++)
                    mma_tf32(acc[mi][ni][0], acc[mi][ni][1], acc[mi][ni][2], acc[mi][ni][3],
                             af[mi][0], af[mi][1], af[mi][2], af[mi][3],
                             bf[ni][0], bf[ni][1]);
        }
    }

    #pragma unroll
    for (int mi = 0; mi < 4; mi++) {
        const int m = m0 + wm + 16 * mi + r;
        #pragma unroll
        for (int ni = 0; ni < 8; ni++) {
            const int n = n0 + wn + 8 * ni + 2 * c;
            const float bx = bias[n], by = bias[n + 1];
            float2 o0 = make_float2(acc[mi][ni][0] + bx, acc[mi][ni][1] + by);
            float2 o1 = make_float2(acc[mi][ni][2] + bx, acc[mi][ni][3] + by);
            *(float2*)(Y + (size_t)m * GEMM_N + n)       = o0;
            *(float2*)(Y + (size_t)(m + 8) * GEMM_N + n) = o1;
        }
    }
}

__global__ __launch_bounds__(128, 3) void qkv_gemm_kernel(
    const float* __restrict__ x1, const float* __restrict__ x2,
    const float* __restrict__ Wq, const float* __restrict__ bq,
    const float* __restrict__ Wk, const float* __restrict__ bk,
    const float* __restrict__ Wv, const float* __restrict__ bv,
    float* __restrict__ Qp, float* __restrict__ Kp, float* __restrict__ Vp)
{
    const float *X, *W, *bias;
    float* Y;
    if (blockIdx.z == 0)      { X = x1; W = Wq; bias = bq; Y = Qp; }
    else if (blockIdx.z == 1) { X = x2; W = Wk; bias = bk; Y = Kp; }
    else                      { X = x2; W = Wv; bias = bv; Y = Vp; }
    gemm_body(X, W, bias, Y);
}

__global__ __launch_bounds__(128, 3) void out_gemm_kernel(
    const float* __restrict__ X, const float* __restrict__ W,
    const float* __restrict__ bias, float* __restrict__ Y)
{
    gemm_body(X, W, bias, Y);
}

// ---------------------------------------------------------------------------
// Flash attention, tf32 MMA, FA2 warp shape + cp.async double-buffered K/V.
// CTA = (b, h, 128-row Q tile). 128 threads = 4 warps; warp w owns rows
// [w*32, w*32+32) as TWO m16 A-fragments. KTILE = 32, two K/V buffers:
// iteration kt waits on its tile, ONE syncthreads, then issues tile kt+1
// before computing — gmem latency fully hidden behind compute.
// K/V stored raw f32 (cp.async is a plain copy); rna-tf32 cvt applied at
// fragment load (FMA pipe ~idle; pointwise => bit-identical results).
// Pitches: Q 68, K 68, V 72 (proven conflict-free), P 36 (=4 mod 32,
// banks 4r+c bijective for the A-frag pattern).
// ---------------------------------------------------------------------------
#define QT      128
#define KTILE   32
#define QP      68
#define KP      68
#define VP      72
#define PP      36

#define QS_OFF  0                         // 128*68 = 8704 floats
#define PS_OFF  8704                      // 128*36 = 4608
#define KS_OFF  (8704 + 4608)             // 2*32*68 = 4352
#define VS_OFF  (8704 + 4608 + 4352)      // 2*32*72 = 4608
#define ATTN_SMEM_FLOATS (VS_OFF + 2 * KTILE * VP)   // 22272 floats = 89088 B

__device__ __forceinline__ void attn_issue_kv(
    uint32_t smem_u32, int buf, int kt, int tid,
    const float* __restrict__ K, const float* __restrict__ V, size_t base)
{
    #pragma unroll
    for (int i = 0; i < 4; i++) {
        const int idx  = i * 128 + tid;       // 512 float4 slots per tile
        const int row  = idx >> 4;            // 0..31
        const int col4 = (idx & 15) * 4;      // 0..60
        const size_t g = base + (size_t)(kt * KTILE + row) * D_MODEL + col4;
        cp_async16(smem_u32 + (uint32_t)((KS_OFF + buf * (KTILE * KP) + row * KP + col4) * 4),
                   K + g);
        cp_async16(smem_u32 + (uint32_t)((VS_OFF + buf * (KTILE * VP) + row * VP + col4) * 4),
                   V + g);
    }
}

__global__ __launch_bounds__(128, 2) void attn_mma_kernel(
    const float* __restrict__ Q, const float* __restrict__ K,
    const float* __restrict__ V, float* __restrict__ O)
{
    extern __shared__ __align__(16) float sm[];
    float* Qs = sm + QS_OFF;
    float* Ps = sm + PS_OFF;
    uint32_t smem_u32 = (uint32_t)__cvta_generic_to_shared(sm);

    const int tid  = threadIdx.x;
    const int lane = tid & 31;
    const int warp = tid >> 5;    // 0..3
    const int r    = lane >> 2;   // fragment row group 0..7
    const int c    = lane & 3;    // fragment k/col group 0..3
    const int wq   = warp * 32;   // warp's 32-row Q strip

    const int q0 = blockIdx.x * QT;
    const int h  = blockIdx.y;
    const int b  = blockIdx.z;
    const size_t base = (size_t)b * SEQ * D_MODEL + (size_t)h * HEAD_DIM;

    // ---- load Q tile (128 x 64) -> Qs (tf32), STS.128 ----
    #pragma unroll
    for (int i = 0; i < 16; i++) {
        const int idx  = i * 128 + tid;       // 2048 float4 slots
        const int row  = idx >> 4;            // 0..127
        const int col4 = (idx & 15) * 4;      // 0..60
        float4 v = *(const float4*)(Q + base + (size_t)(q0 + row) * D_MODEL + col4);
        *(float4*)&Qs[row * QP + col4] =
            make_float4(f2tf32(v.x), f2tf32(v.y), f2tf32(v.z), f2tf32(v.w));
    }

    float oacc[2][8][4];
    float mv[2][2], lv[2][2];
    #pragma unroll
    for (int mi = 0; mi < 2; mi++) {
        mv[mi][0] = -1e30f; mv[mi][1] = -1e30f;
        lv[mi][0] = 0.f;    lv[mi][1] = 0.f;
        #pragma unroll
        for (int i = 0; i < 8; i++)
            #pragma unroll
            for (int j = 0; j < 4; j++) oacc[mi][i][j] = 0.f;
    }

    const float scale = 0.125f;   // 1/sqrt(64)
    const int nTiles  = SEQ / KTILE;   // 64

    // prologue: tile 0 in flight
    attn_issue_kv(smem_u32, 0, 0, tid, K, V, base);
    CP_COMMIT();

    for (int kt = 0; kt < nTiles; kt++) {
        const int buf = kt & 1;
        const float* Ks = sm + KS_OFF + buf * (KTILE * KP);
        const float* Vs = sm + VS_OFF + buf * (KTILE * VP);

        CP_WAIT(0);          // tile kt landed (only outstanding group)
        __syncthreads();     // visible to all; prev iter's reads of buf^1 done

        if (kt + 1 < nTiles) {
            attn_issue_kv(smem_u32, buf ^ 1, kt + 1, tid, K, V, base);
            CP_COMMIT();     // overlaps with compute below
        }

        // ---- S = Q·K^T : 32 x 32 per warp ----
        float sacc[2][4][4];
        #pragma unroll
        for (int mi = 0; mi < 2; mi++)
            #pragma unroll
            for (int i = 0; i < 4; i++)
                #pragma unroll
                for (int j = 0; j < 4; j++) sacc[mi][i][j] = 0.f;

        #pragma unroll
        for (int kk = 0; kk < 8; kk++) {
            const int kb = kk * 8;
            float af[2][4];
            #pragma unroll
            for (int mi = 0; mi < 2; mi++) {
                const int rb = wq + mi * 16;
                af[mi][0] = Qs[(rb + r    ) * QP + kb + c    ];
                af[mi][1] = Qs[(rb + r + 8) * QP + kb + c    ];
                af[mi][2] = Qs[(rb + r    ) * QP + kb + c + 4];
                af[mi][3] = Qs[(rb + r + 8) * QP + kb + c + 4];
            }
            #pragma unroll
            for (int nt = 0; nt < 4; nt++) {
                float b0 = f2tf32(Ks[(nt * 8 + r) * KP + kb + c    ]);
                float b1 = f2tf32(Ks[(nt * 8 + r) * KP + kb + c + 4]);
                #pragma unroll
                for (int mi = 0; mi < 2; mi++)
                    mma_tf32(sacc[mi][nt][0], sacc[mi][nt][1], sacc[mi][nt][2], sacc[mi][nt][3],
                             af[mi][0], af[mi][1], af[mi][2], af[mi][3], b0, b1);
            }
        }

        // ---- online softmax per m-frag ----
        #pragma unroll
        for (int mi = 0; mi < 2; mi++) {
            float mx0 = -1e30f, mx1 = -1e30f;
            #pragma unroll
            for (int nt = 0; nt < 4; nt++) {
                sacc[mi][nt][0] *= scale; sacc[mi][nt][1] *= scale;
                sacc[mi][nt][2] *= scale; sacc[mi][nt][3] *= scale;
                mx0 = fmaxf(mx0, fmaxf(sacc[mi][nt][0], sacc[mi][nt][1]));
                mx1 = fmaxf(mx1, fmaxf(sacc[mi][nt][2], sacc[mi][nt][3]));
            }
            mx0 = fmaxf(mx0, __shfl_xor_sync(0xffffffffu, mx0, 1));
            mx0 = fmaxf(mx0, __shfl_xor_sync(0xffffffffu, mx0, 2));
            mx1 = fmaxf(mx1, __shfl_xor_sync(0xffffffffu, mx1, 1));
            mx1 = fmaxf(mx1, __shfl_xor_sync(0xffffffffu, mx1, 2));

            const float mn0 = fmaxf(mv[mi][0], mx0);
            const float mn1 = fmaxf(mv[mi][1], mx1);
            const float corr0 = __expf(mv[mi][0] - mn0);
            const float corr1 = __expf(mv[mi][1] - mn1);
            mv[mi][0] = mn0; mv[mi][1] = mn1;

            float rs0 = 0.f, rs1 = 0.f;
            #pragma unroll
            for (int nt = 0; nt < 4; nt++) {
                sacc[mi][nt][0] = __expf(sacc[mi][nt][0] - mn0);
                sacc[mi][nt][1] = __expf(sacc[mi][nt][1] - mn0);
                sacc[mi][nt][2] = __expf(sacc[mi][nt][2] - mn1);
                sacc[mi][nt][3] = __expf(sacc[mi][nt][3] - mn1);
                rs0 += sacc[mi][nt][0] + sacc[mi][nt][1];
                rs1 += sacc[mi][nt][2] + sacc[mi][nt][3];
            }
            rs0 += __shfl_xor_sync(0xffffffffu, rs0, 1);
            rs0 += __shfl_xor_sync(0xffffffffu, rs0, 2);
            rs1 += __shfl_xor_sync(0xffffffffu, rs1, 1);
            rs1 += __shfl_xor_sync(0xffffffffu, rs1, 2);

            lv[mi][0] = lv[mi][0] * corr0 + rs0;
            lv[mi][1] = lv[mi][1] * corr1 + rs1;
            #pragma unroll
            for (int nt = 0; nt < 8; nt++) {
                oacc[mi][nt][0] *= corr0; oacc[mi][nt][1] *= corr0;
                oacc[mi][nt][2] *= corr1; oacc[mi][nt][3] *= corr1;
            }

            // write P (accumulator layout) to warp-private smem rows
            const int rb = wq + mi * 16;
            #pragma unroll
            for (int nt = 0; nt < 4; nt++) {
                float2 p0 = make_float2(f2tf32(sacc[mi][nt][0]), f2tf32(sacc[mi][nt][1]));
                float2 p1 = make_float2(f2tf32(sacc[mi][nt][2]), f2tf32(sacc[mi][nt][3]));
                *(float2*)&Ps[(rb + r    ) * PP + nt * 8 + 2 * c] = p0;
                *(float2*)&Ps[(rb + r + 8) * PP + nt * 8 + 2 * c] = p1;
            }
        }
        __syncwarp();   // P rows warp-private

        // ---- O += P·V : 4 seq k-steps x 8 d-tiles ----
        #pragma unroll
        for (int kk = 0; kk < 4; kk++) {
            const int kb = kk * 8;
            float af[2][4];
            #pragma unroll
            for (int mi = 0; mi < 2; mi++) {
                const int rb = wq + mi * 16;
                af[mi][0] = Ps[(rb + r    ) * PP + kb + c    ];
                af[mi][1] = Ps[(rb + r + 8) * PP + kb + c    ];
                af[mi][2] = Ps[(rb + r    ) * PP + kb + c + 4];
                af[mi][3] = Ps[(rb + r + 8) * PP + kb + c + 4];
            }
            #pragma unroll
            for (int nt = 0; nt < 8; nt++) {
                float b0 = f2tf32(Vs[(kb + c    ) * VP + nt * 8 + r]);
                float b1 = f2tf32(Vs[(kb + c + 4) * VP + nt * 8 + r]);
                #pragma unroll
                for (int mi = 0; mi < 2; mi++)
                    mma_tf32(oacc[mi][nt][0], oacc[mi][nt][1], oacc[mi][nt][2], oacc[mi][nt][3],
                             af[mi][0], af[mi][1], af[mi][2], af[mi][3], b0, b1);
            }
        }
    }

    // ---- normalize and write context ----
    #pragma unroll
    for (int mi = 0; mi < 2; mi++) {
        const float inv0 = 1.0f / lv[mi][0];
        const float inv1 = 1.0f / lv[mi][1];
        const int rb = wq + mi * 16;
        #pragma unroll
        for (int nt = 0; nt < 8; nt++) {
            const int col = nt * 8 + 2 * c;
            float2 o0 = make_float2(oacc[mi][nt][0] * inv0, oacc[mi][nt][1] * inv0);
            float2 o1 = make_float2(oacc[mi][nt][2] * inv1, oacc[mi][nt][3] * inv1);
            *(float2*)(O + base + (size_t)(q0 + rb + r    ) * D_MODEL + col) = o0;
            *(float2*)(O + base + (size_t)(q0 + rb + r + 8) * D_MODEL + col) = o1;
        }
    }
}

// ---------------------------------------------------------------------------
// Launch: merged QKV projection -> attention -> output projection
// Inputs (metadata order): x1, x2, Wq, bq, Wk, bk, Wv, bv, Wo, bo
// ---------------------------------------------------------------------------
extern "C" void kernel_launch(void* const* d_in, const int* in_sizes, int n_in,
                              void* d_out, int out_size)
{
    (void)in_sizes; (void)n_in; (void)out_size;

    const float* x1 = (const float*)d_in[0];
    const float* x2 = (const float*)d_in[1];
    const float* Wq = (const float*)d_in[2];
    const float* bq = (const float*)d_in[3];
    const float* Wk = (const float*)d_in[4];
    const float* bk = (const float*)d_in[5];
    const float* Wv = (const float*)d_in[6];
    const float* bv = (const float*)d_in[7];
    const float* Wo = (const float*)d_in[8];
    const float* bo = (const float*)d_in[9];
    float* out = (float*)d_out;

    float *Qp, *Kp, *Vp, *Cp;
    cudaGetSymbolAddress((void**)&Qp, g_Q);
    cudaGetSymbolAddress((void**)&Kp, g_K);
    cudaGetSymbolAddress((void**)&Vp, g_V);
    cudaGetSymbolAddress((void**)&Cp, g_C);

    const int gemm_smem = GEMM_SMEM_FLOATS * (int)sizeof(float);   // 56064 B
    cudaFuncSetAttribute(qkv_gemm_kernel,
                         cudaFuncAttributeMaxDynamicSharedMemorySize, gemm_smem);
    cudaFuncSetAttribute(out_gemm_kernel,
                         cudaFuncAttributeMaxDynamicSharedMemorySize, gemm_smem);

    const int attn_smem = ATTN_SMEM_FLOATS * (int)sizeof(float);   // 89088 B
    cudaFuncSetAttribute(attn_mma_kernel,
                         cudaFuncAttributeMaxDynamicSharedMemorySize, attn_smem);

    dim3 qkv_grid(GEMM_N / 128, GEMM_M / 128, 3);   // (8, 32, 3)
    qkv_gemm_kernel<<<qkv_grid, 128, gemm_smem>>>(x1, x2, Wq, bq, Wk, bk, Wv, bv,
                                                  Qp, Kp, Vp);

    dim3 attn_grid(SEQ / QT, NUM_HEADS, B_SZ);      // (16, 16, 2)
    attn_mma_kernel<<<attn_grid, 128, attn_smem>>>(Qp, Kp, Vp, Cp);

    dim3 out_grid(GEMM_N / 128, GEMM_M / 128);      // (8, 32)
    out_gemm_kernel<<<out_grid, 128, gemm_smem>>>(Cp, Wo, bo, out);
}

// round 15
// speedup vs baseline: 1.6227x; 1.6227x over previous
#include <cuda_runtime.h>
#include <cstdint>
#include <cmath>

// Problem constants (fixed by the reference)
#define D_MODEL   1024
#define NUM_HEADS 16
#define HEAD_DIM  64
#define B_SZ      2
#define SEQ       2048
#define M_TOT     (B_SZ * SEQ)   // 4096 rows for all projection GEMMs

// Scratch (allocation-free rule: __device__ globals). 4 x 16 MB = 64 MB.
__device__ float g_Q[(size_t)M_TOT * D_MODEL];
__device__ float g_K[(size_t)M_TOT * D_MODEL];
__device__ float g_V[(size_t)M_TOT * D_MODEL];
__device__ float g_C[(size_t)M_TOT * D_MODEL];

// ---------------------------------------------------------------------------
// tf32 / cp.async helpers
// ---------------------------------------------------------------------------
__device__ __forceinline__ float f2tf32(float x) {
    asm("cvt.rna.tf32.f32 %0, %0;" : "+f"(x));
    return x;
}

__device__ __forceinline__ void mma_tf32(float& c0, float& c1, float& c2, float& c3,
                                         float a0, float a1, float a2, float a3,
                                         float b0, float b1)
{
    asm volatile(
        "mma.sync.aligned.m16n8k8.row.col.f32.tf32.tf32.f32 "
        "{%0,%1,%2,%3}, {%4,%5,%6,%7}, {%8,%9}, {%0,%1,%2,%3};\n"
        : "+f"(c0), "+f"(c1), "+f"(c2), "+f"(c3)
        : "r"(__float_as_uint(a0)), "r"(__float_as_uint(a1)),
          "r"(__float_as_uint(a2)), "r"(__float_as_uint(a3)),
          "r"(__float_as_uint(b0)), "r"(__float_as_uint(b1)));
}

__device__ __forceinline__ void cp_async16(uint32_t dst, const void* src) {
    asm volatile("cp.async.cg.shared.global [%0], [%1], 16;\n" :: "r"(dst), "l"(src));
}
#define CP_COMMIT() asm volatile("cp.async.commit_group;\n" ::: "memory")
#define CP_WAIT(n)  asm volatile("cp.async.wait_group %0;\n" :: "n"(n) : "memory")

// ---------------------------------------------------------------------------
// GEMM + bias (tf32 tensor cores, cp.async 3-stage pipeline, 3 CTAs/SM)
// (unchanged — proven at 553.9us)
// ---------------------------------------------------------------------------
#define GEMM_M   4096
#define GEMM_N   1024
#define GEMM_K   1024
#define AP       20
#define BPITCH   132
#define A_STAGE  (128 * AP)     // 2560 floats
#define B_STAGE  (16 * BPITCH)  // 2112 floats
#define NSTAGE   3
#define GEMM_SMEM_FLOATS (NSTAGE * (A_STAGE + B_STAGE))   // 14016 -> 56064 B

__device__ __forceinline__ void gemm_issue_stage(
    uint32_t smem_u32, int s, int k0, int tid,
    const float* __restrict__ X, const float* __restrict__ W,
    int m0, int n0)
{
    #pragma unroll
    for (int i = 0; i < 4; i++) {
        const int idx = i * 128 + tid;
        const int m   = idx >> 2;
        const int ko  = (idx & 3) * 4;
        const float* src = X + (size_t)(m0 + m) * GEMM_K + k0 + ko;
        uint32_t dst = smem_u32 + (uint32_t)((s * A_STAGE + m * AP + ko) * 4);
        cp_async16(dst, src);
    }
    #pragma unroll
    for (int i = 0; i < 4; i++) {
        const int idx = i * 128 + tid;
        const int k   = idx >> 5;
        const int n4  = (idx & 31) * 4;
        const float* src = W + (size_t)(k0 + k) * GEMM_N + n0 + n4;
        uint32_t dst = smem_u32 +
            (uint32_t)((NSTAGE * A_STAGE + s * B_STAGE + k * BPITCH + n4) * 4);
        cp_async16(dst, src);
    }
}

__device__ __forceinline__ void gemm_body(
    const float* __restrict__ X, const float* __restrict__ W,
    const float* __restrict__ bias, float* __restrict__ Y)
{
    extern __shared__ __align__(16) float gsm[];
    uint32_t smem_u32 = (uint32_t)__cvta_generic_to_shared(gsm);

    const int tid  = threadIdx.x;
    const int lane = tid & 31;
    const int warp = tid >> 5;           // 0..3
    const int wm   = (warp >> 1) * 64;
    const int wn   = (warp & 1) * 64;
    const int r    = lane >> 2;
    const int c    = lane & 3;

    const int m0 = blockIdx.y * 128;
    const int n0 = blockIdx.x * 128;

    float acc[4][8][4];
    #pragma unroll
    for (int i = 0; i < 4; i++)
        #pragma unroll
        for (int j = 0; j < 8; j++)
            #pragma unroll
            for (int q = 0; q < 4; q++) acc[i][j][q] = 0.f;

    const int nIter = GEMM_K / 16;   // 64

    #pragma unroll
    for (int s = 0; s < NSTAGE - 1; s++) {
        gemm_issue_stage(smem_u32, s, s * 16, tid, X, W, m0, n0);
        CP_COMMIT();
    }

    for (int it = 0; it < nIter; it++) {
        CP_WAIT(NSTAGE - 2);
        __syncthreads();

        if (it + NSTAGE - 1 < nIter)
            gemm_issue_stage(smem_u32, (it + NSTAGE - 1) % NSTAGE,
                             (it + NSTAGE - 1) * 16, tid, X, W, m0, n0);
        CP_COMMIT();

        const int buf = it % NSTAGE;
        const float* Ab = gsm + buf * A_STAGE;
        const float* Bb = gsm + NSTAGE * A_STAGE + buf * B_STAGE;

        #pragma unroll
        for (int s = 0; s < 2; s++) {
            const int kb = s * 8;
            float af[4][4], bf[8][2];
            #pragma unroll
            for (int mi = 0; mi < 4; mi++) {
                const int mb = wm + 16 * mi;
                af[mi][0] = f2tf32(Ab[(mb + r    ) * AP + kb + c    ]);
                af[mi][1] = f2tf32(Ab[(mb + r + 8) * AP + kb + c    ]);
                af[mi][2] = f2tf32(Ab[(mb + r    ) * AP + kb + c + 4]);
                af[mi][3] = f2tf32(Ab[(mb + r + 8) * AP + kb + c + 4]);
            }
            #pragma unroll
            for (int ni = 0; ni < 8; ni++) {
                const int nb = wn + 8 * ni;
                bf[ni][0] = f2tf32(Bb[(kb + c    ) * BPITCH + nb + r]);
                bf[ni][1] = f2tf32(Bb[(kb + c + 4) * BPITCH + nb + r]);
            }
            #pragma unroll
            for (int mi = 0; mi < 4; mi++)
                #pragma unroll
                for (int ni = 0; ni < 8; ni++)
                    mma_tf32(acc[mi][ni][0], acc[mi][ni][1], acc[mi][ni][2], acc[mi][ni][3],
                             af[mi][0], af[mi][1], af[mi][2], af[mi][3],
                             bf[ni][0], bf[ni][1]);
        }
    }

    #pragma unroll
    for (int mi = 0; mi < 4; mi++) {
        const int m = m0 + wm + 16 * mi + r;
        #pragma unroll
        for (int ni = 0; ni < 8; ni++) {
            const int n = n0 + wn + 8 * ni + 2 * c;
            const float bx = bias[n], by = bias[n + 1];
            float2 o0 = make_float2(acc[mi][ni][0] + bx, acc[mi][ni][1] + by);
            float2 o1 = make_float2(acc[mi][ni][2] + bx, acc[mi][ni][3] + by);
            *(float2*)(Y + (size_t)m * GEMM_N + n)       = o0;
            *(float2*)(Y + (size_t)(m + 8) * GEMM_N + n) = o1;
        }
    }
}

__global__ __launch_bounds__(128, 3) void qkv_gemm_kernel(
    const float* __restrict__ x1, const float* __restrict__ x2,
    const float* __restrict__ Wq, const float* __restrict__ bq,
    const float* __restrict__ Wk, const float* __restrict__ bk,
    const float* __restrict__ Wv, const float* __restrict__ bv,
    float* __restrict__ Qp, float* __restrict__ Kp, float* __restrict__ Vp)
{
    const float *X, *W, *bias;
    float* Y;
    if (blockIdx.z == 0)      { X = x1; W = Wq; bias = bq; Y = Qp; }
    else if (blockIdx.z == 1) { X = x2; W = Wk; bias = bk; Y = Kp; }
    else                      { X = x2; W = Wv; bias = bv; Y = Vp; }
    gemm_body(X, W, bias, Y);
}

__global__ __launch_bounds__(128, 3) void out_gemm_kernel(
    const float* __restrict__ X, const float* __restrict__ W,
    const float* __restrict__ bias, float* __restrict__ Y)
{
    gemm_body(X, W, bias, Y);
}

// ---------------------------------------------------------------------------
// Flash attention, tf32 MMA, FA2 warp shape, KTILE=64 (R13 iteration economy)
// + Q fragments hoisted to REGISTERS + cp.async double-buffered K/V.
// CTA = (b, h, 128-row Q tile). 128 threads = 4 warps; warp w owns rows
// [w*32, w*32+32) as TWO m16 A-fragments.
// Q A-frags (64 floats/thread) are loop-invariant: loaded once from gmem,
// freeing 8.7 KB smem and ~64 LDS.32 per thread per iteration.
// K/V double-buffered via cp.async: wait tile kt -> one sync -> issue kt+1
// -> compute. f2tf32 applied at fragment load (pointwise, bit-identical).
// Pitches: K 68, V 72, P 68 (all proven conflict-free).
// ---------------------------------------------------------------------------
#define QT      128
#define KTILE   64
#define KP      68
#define VP      72
#define PP      68

#define PS_OFF  0                          // 128*68 = 8704 floats
#define KS_OFF  8704                       // 2*64*68 = 8704
#define VS_OFF  (8704 + 8704)              // 2*64*72 = 9216
#define ATTN_SMEM_FLOATS (VS_OFF + 2 * KTILE * VP)   // 26624 floats = 106496 B

__device__ __forceinline__ void attn_issue_kv(
    uint32_t smem_u32, int buf, int kt, int tid,
    const float* __restrict__ K, const float* __restrict__ V, size_t base)
{
    #pragma unroll
    for (int i = 0; i < 8; i++) {
        const int idx  = i * 128 + tid;       // 1024 float4 slots per tile
        const int row  = idx >> 4;            // 0..63
        const int col4 = (idx & 15) * 4;      // 0..60
        const size_t g = base + (size_t)(kt * KTILE + row) * D_MODEL + col4;
        cp_async16(smem_u32 + (uint32_t)((KS_OFF + buf * (KTILE * KP) + row * KP + col4) * 4),
                   K + g);
        cp_async16(smem_u32 + (uint32_t)((VS_OFF + buf * (KTILE * VP) + row * VP + col4) * 4),
                   V + g);
    }
}

__global__ __launch_bounds__(128, 2) void attn_mma_kernel(
    const float* __restrict__ Q, const float* __restrict__ K,
    const float* __restrict__ V, float* __restrict__ O)
{
    extern __shared__ __align__(16) float sm[];
    float* Ps = sm + PS_OFF;
    uint32_t smem_u32 = (uint32_t)__cvta_generic_to_shared(sm);

    const int tid  = threadIdx.x;
    const int lane = tid & 31;
    const int warp = tid >> 5;    // 0..3
    const int r    = lane >> 2;   // fragment row group 0..7
    const int c    = lane & 3;    // fragment k/col group 0..3
    const int wq   = warp * 32;   // warp's 32-row Q strip

    const int q0 = blockIdx.x * QT;
    const int h  = blockIdx.y;
    const int b  = blockIdx.z;
    const size_t base = (size_t)b * SEQ * D_MODEL + (size_t)h * HEAD_DIM;

    // ---- load Q A-fragments directly from gmem into registers (once) ----
    // qreg[kk][mi][j]: j layout matches the mma A operand.
    float qreg[8][2][4];
    {
        const float* Qg = Q + base;
        #pragma unroll
        for (int kk = 0; kk < 8; kk++) {
            const int kb = kk * 8;
            #pragma unroll
            for (int mi = 0; mi < 2; mi++) {
                const int rb = q0 + wq + mi * 16;
                qreg[kk][mi][0] = f2tf32(Qg[(size_t)(rb + r    ) * D_MODEL + kb + c    ]);
                qreg[kk][mi][1] = f2tf32(Qg[(size_t)(rb + r + 8) * D_MODEL + kb + c    ]);
                qreg[kk][mi][2] = f2tf32(Qg[(size_t)(rb + r    ) * D_MODEL + kb + c + 4]);
                qreg[kk][mi][3] = f2tf32(Qg[(size_t)(rb + r + 8) * D_MODEL + kb + c + 4]);
            }
        }
    }

    float oacc[2][8][4];
    float mv[2][2], lv[2][2];
    #pragma unroll
    for (int mi = 0; mi < 2; mi++) {
        mv[mi][0] = -1e30f; mv[mi][1] = -1e30f;
        lv[mi][0] = 0.f;    lv[mi][1] = 0.f;
        #pragma unroll
        for (int i = 0; i < 8; i++)
            #pragma unroll
            for (int j = 0; j < 4; j++) oacc[mi][i][j] = 0.f;
    }

    const float scale = 0.125f;        // 1/sqrt(64)
    const int nTiles  = SEQ / KTILE;   // 32

    // prologue: tile 0 in flight
    attn_issue_kv(smem_u32, 0, 0, tid, K, V, base);
    CP_COMMIT();

    for (int kt = 0; kt < nTiles; kt++) {
        const int buf = kt & 1;
        const float* Ks = sm + KS_OFF + buf * (KTILE * KP);
        const float* Vs = sm + VS_OFF + buf * (KTILE * VP);

        CP_WAIT(0);          // tile kt landed (only outstanding group)
        __syncthreads();     // visible to all; prev iter's reads of buf^1 done

        if (kt + 1 < nTiles) {
            attn_issue_kv(smem_u32, buf ^ 1, kt + 1, tid, K, V, base);
            CP_COMMIT();     // overlaps with compute below
        }

        // ---- S = Q·K^T : 32 x 64 per warp; Q from registers ----
        float sacc[2][8][4];
        #pragma unroll
        for (int mi = 0; mi < 2; mi++)
            #pragma unroll
            for (int i = 0; i < 8; i++)
                #pragma unroll
                for (int j = 0; j < 4; j++) sacc[mi][i][j] = 0.f;

        #pragma unroll
        for (int kk = 0; kk < 8; kk++) {
            const int kb = kk * 8;
            #pragma unroll
            for (int nt = 0; nt < 8; nt++) {
                float b0 = f2tf32(Ks[(nt * 8 + r) * KP + kb + c    ]);
                float b1 = f2tf32(Ks[(nt * 8 + r) * KP + kb + c + 4]);
                #pragma unroll
                for (int mi = 0; mi < 2; mi++)
                    mma_tf32(sacc[mi][nt][0], sacc[mi][nt][1], sacc[mi][nt][2], sacc[mi][nt][3],
                             qreg[kk][mi][0], qreg[kk][mi][1],
                             qreg[kk][mi][2], qreg[kk][mi][3], b0, b1);
            }
        }

        // ---- online softmax per m-frag (rows r and r+8 within each) ----
        #pragma unroll
        for (int mi = 0; mi < 2; mi++) {
            float mx0 = -1e30f, mx1 = -1e30f;
            #pragma unroll
            for (int nt = 0; nt < 8; nt++) {
                sacc[mi][nt][0] *= scale; sacc[mi][nt][1] *= scale;
                sacc[mi][nt][2] *= scale; sacc[mi][nt][3] *= scale;
                mx0 = fmaxf(mx0, fmaxf(sacc[mi][nt][0], sacc[mi][nt][1]));
                mx1 = fmaxf(mx1, fmaxf(sacc[mi][nt][2], sacc[mi][nt][3]));
            }
            mx0 = fmaxf(mx0, __shfl_xor_sync(0xffffffffu, mx0, 1));
            mx0 = fmaxf(mx0, __shfl_xor_sync(0xffffffffu, mx0, 2));
            mx1 = fmaxf(mx1, __shfl_xor_sync(0xffffffffu, mx1, 1));
            mx1 = fmaxf(mx1, __shfl_xor_sync(0xffffffffu, mx1, 2));

            const float mn0 = fmaxf(mv[mi][0], mx0);
            const float mn1 = fmaxf(mv[mi][1], mx1);
            const float corr0 = __expf(mv[mi][0] - mn0);
            const float corr1 = __expf(mv[mi][1] - mn1);
            mv[mi][0] = mn0; mv[mi][1] = mn1;

            float rs0 = 0.f, rs1 = 0.f;
            #pragma unroll
            for (int nt = 0; nt < 8; nt++) {
                sacc[mi][nt][0] = __expf(sacc[mi][nt][0] - mn0);
                sacc[mi][nt][1] = __expf(sacc[mi][nt][1] - mn0);
                sacc[mi][nt][2] = __expf(sacc[mi][nt][2] - mn1);
                sacc[mi][nt][3] = __expf(sacc[mi][nt][3] - mn1);
                rs0 += sacc[mi][nt][0] + sacc[mi][nt][1];
                rs1 += sacc[mi][nt][2] + sacc[mi][nt][3];
            }
            rs0 += __shfl_xor_sync(0xffffffffu, rs0, 1);
            rs0 += __shfl_xor_sync(0xffffffffu, rs0, 2);
            rs1 += __shfl_xor_sync(0xffffffffu, rs1, 1);
            rs1 += __shfl_xor_sync(0xffffffffu, rs1, 2);

            lv[mi][0] = lv[mi][0] * corr0 + rs0;
            lv[mi][1] = lv[mi][1] * corr1 + rs1;
            #pragma unroll
            for (int nt = 0; nt < 8; nt++) {
                oacc[mi][nt][0] *= corr0; oacc[mi][nt][1] *= corr0;
                oacc[mi][nt][2] *= corr1; oacc[mi][nt][3] *= corr1;
            }

            // write P (accumulator layout) to warp-private smem rows
            const int rb = wq + mi * 16;
            #pragma unroll
            for (int nt = 0; nt < 8; nt++) {
                float2 p0 = make_float2(f2tf32(sacc[mi][nt][0]), f2tf32(sacc[mi][nt][1]));
                float2 p1 = make_float2(f2tf32(sacc[mi][nt][2]), f2tf32(sacc[mi][nt][3]));
                *(float2*)&Ps[(rb + r    ) * PP + nt * 8 + 2 * c] = p0;
                *(float2*)&Ps[(rb + r + 8) * PP + nt * 8 + 2 * c] = p1;
            }
        }
        __syncwarp();   // P rows warp-private

        // ---- O += P·V : 8 seq k-steps x 8 d-tiles; B frags shared ----
        #pragma unroll
        for (int kk = 0; kk < 8; kk++) {
            const int kb = kk * 8;
            float af[2][4];
            #pragma unroll
            for (int mi = 0; mi < 2; mi++) {
                const int rb = wq + mi * 16;
                af[mi][0] = Ps[(rb + r    ) * PP + kb + c    ];
                af[mi][1] = Ps[(rb + r + 8) * PP + kb + c    ];
                af[mi][2] = Ps[(rb + r    ) * PP + kb + c + 4];
                af[mi][3] = Ps[(rb + r + 8) * PP + kb + c + 4];
            }
            #pragma unroll
            for (int nt = 0; nt < 8; nt++) {
                float b0 = f2tf32(Vs[(kb + c    ) * VP + nt * 8 + r]);
                float b1 = f2tf32(Vs[(kb + c + 4) * VP + nt * 8 + r]);
                #pragma unroll
                for (int mi = 0; mi < 2; mi++)
                    mma_tf32(oacc[mi][nt][0], oacc[mi][nt][1], oacc[mi][nt][2], oacc[mi][nt][3],
                             af[mi][0], af[mi][1], af[mi][2], af[mi][3], b0, b1);
            }
        }
    }

    // ---- normalize and write context ----
    #pragma unroll
    for (int mi = 0; mi < 2; mi++) {
        const float inv0 = 1.0f / lv[mi][0];
        const float inv1 = 1.0f / lv[mi][1];
        const int rb = wq + mi * 16;
        #pragma unroll
        for (int nt = 0; nt < 8; nt++) {
            const int col = nt * 8 + 2 * c;
            float2 o0 = make_float2(oacc[mi][nt][0] * inv0, oacc[mi][nt][1] * inv0);
            float2 o1 = make_float2(oacc[mi][nt][2] * inv1, oacc[mi][nt][3] * inv1);
            *(float2*)(O + base + (size_t)(q0 + rb + r    ) * D_MODEL + col) = o0;
            *(float2*)(O + base + (size_t)(q0 + rb + r + 8) * D_MODEL + col) = o1;
        }
    }
}

// ---------------------------------------------------------------------------
// Launch: merged QKV projection -> attention -> output projection
// Inputs (metadata order): x1, x2, Wq, bq, Wk, bk, Wv, bv, Wo, bo
// ---------------------------------------------------------------------------
extern "C" void kernel_launch(void* const* d_in, const int* in_sizes, int n_in,
                              void* d_out, int out_size)
{
    (void)in_sizes; (void)n_in; (void)out_size;

    const float* x1 = (const float*)d_in[0];
    const float* x2 = (const float*)d_in[1];
    const float* Wq = (const float*)d_in[2];
    const float* bq = (const float*)d_in[3];
    const float* Wk = (const float*)d_in[4];
    const float* bk = (const float*)d_in[5];
    const float* Wv = (const float*)d_in[6];
    const float* bv = (const float*)d_in[7];
    const float* Wo = (const float*)d_in[8];
    const float* bo = (const float*)d_in[9];
    float* out = (float*)d_out;

    float *Qp, *Kp, *Vp, *Cp;
    cudaGetSymbolAddress((void**)&Qp, g_Q);
    cudaGetSymbolAddress((void**)&Kp, g_K);
    cudaGetSymbolAddress((void**)&Vp, g_V);
    cudaGetSymbolAddress((void**)&Cp, g_C);

    const int gemm_smem = GEMM_SMEM_FLOATS * (int)sizeof(float);   // 56064 B
    cudaFuncSetAttribute(qkv_gemm_kernel,
                         cudaFuncAttributeMaxDynamicSharedMemorySize, gemm_smem);
    cudaFuncSetAttribute(out_gemm_kernel,
                         cudaFuncAttributeMaxDynamicSharedMemorySize, gemm_smem);

    const int attn_smem = ATTN_SMEM_FLOATS * (int)sizeof(float);   // 106496 B
    cudaFuncSetAttribute(attn_mma_kernel,
                         cudaFuncAttributeMaxDynamicSharedMemorySize, attn_smem);

    dim3 qkv_grid(GEMM_N / 128, GEMM_M / 128, 3);   // (8, 32, 3)
    qkv_gemm_kernel<<<qkv_grid, 128, gemm_smem>>>(x1, x2, Wq, bq, Wk, bk, Wv, bv,
                                                  Qp, Kp, Vp);

    dim3 attn_grid(SEQ / QT, NUM_HEADS, B_SZ);      // (16, 16, 2)
    attn_mma_kernel<<<attn_grid, 128, attn_smem>>>(Qp, Kp, Vp, Cp);

    dim3 out_grid(GEMM_N / 128, GEMM_M / 128);      // (8, 32)
    out_gemm_kernel<<<out_grid, 128, gemm_smem>>>(Cp, Wo, bo, out);
}